// round 2
// baseline (speedup 1.0000x reference)
#include <cuda_runtime.h>
#include <math.h>

#define E_ 8
#define D_ 1024
#define H_ 2048
#define O_ 1024
#define B_ 4096
#define S_ 8192   // total dispatched rows = TOP_K * B

// -------- scratch (device globals: allocation-guard-safe) --------
__device__ __align__(16) float g_h1[S_ * H_];   // 64 MB
__device__ __align__(16) float g_h2[S_ * H_];   // 64 MB
__device__ __align__(16) float g_eo[S_ * O_];   // 32 MB
__device__ int   g_rows[S_];     // slot -> token id
__device__ int   g_slot[S_];     // (b*2+k) -> slot
__device__ int   g_eidx[S_];     // (b*2+k) -> expert
__device__ float g_wt[S_];       // (b*2+k) -> gate weight
__device__ int   g_cnt[E_];
__device__ int   g_off[E_ + 1];
__device__ int   g_cur[E_];

struct XPtrs { const float* p[E_]; };

// -------- setup kernels --------
__global__ void k_zero() {
    int t = threadIdx.x;
    if (t < E_) g_cnt[t] = 0;
}

__global__ void k_gate(XPtrs xs, const float* __restrict__ gw,
                       const float* __restrict__ gb) {
    int b = blockIdx.x;
    int tid = threadIdx.x;  // 256
    float acc[E_];
#pragma unroll
    for (int e = 0; e < E_; e++) acc[e] = 0.f;
    for (int j = tid; j < E_ * D_; j += 256) {
        float v = xs.p[j >> 10][b * D_ + (j & (D_ - 1))];
        const float4* wr = (const float4*)(gw + (long)j * E_);
        float4 w0 = wr[0], w1 = wr[1];
        acc[0] = fmaf(v, w0.x, acc[0]); acc[1] = fmaf(v, w0.y, acc[1]);
        acc[2] = fmaf(v, w0.z, acc[2]); acc[3] = fmaf(v, w0.w, acc[3]);
        acc[4] = fmaf(v, w1.x, acc[4]); acc[5] = fmaf(v, w1.y, acc[5]);
        acc[6] = fmaf(v, w1.z, acc[6]); acc[7] = fmaf(v, w1.w, acc[7]);
    }
#pragma unroll
    for (int off = 16; off > 0; off >>= 1)
#pragma unroll
        for (int e = 0; e < E_; e++)
            acc[e] += __shfl_down_sync(0xffffffffu, acc[e], off);
    __shared__ float s[8][E_];
    int w = tid >> 5, lane = tid & 31;
    if (lane == 0)
#pragma unroll
        for (int e = 0; e < E_; e++) s[w][e] = acc[e];
    __syncthreads();
    if (tid == 0) {
        float lg[E_];
#pragma unroll
        for (int e = 0; e < E_; e++) {
            float t = gb[e];
#pragma unroll
            for (int ww = 0; ww < 8; ww++) t += s[ww][e];
            lg[e] = t;
        }
        // top-2, lower index wins on ties (matches lax.top_k)
        int i0 = 0;
        for (int e = 1; e < E_; e++) if (lg[e] > lg[i0]) i0 = e;
        int i1 = (i0 == 0) ? 1 : 0;
        for (int e = 0; e < E_; e++) if (e != i0 && lg[e] > lg[i1]) i1 = e;
        float ex = expf(lg[i1] - lg[i0]);   // <= 1, stable
        float inv = 1.f / (1.f + ex);
        g_eidx[2 * b] = i0; g_eidx[2 * b + 1] = i1;
        g_wt[2 * b] = inv;  g_wt[2 * b + 1] = ex * inv;
        atomicAdd(&g_cnt[i0], 1);
        atomicAdd(&g_cnt[i1], 1);
    }
}

__global__ void k_scan() {
    if (threadIdx.x == 0) {
        int acc = 0;
        for (int e = 0; e < E_; e++) { g_off[e] = acc; g_cur[e] = acc; acc += g_cnt[e]; }
        g_off[E_] = acc;
    }
}

__global__ void k_fill() {
    int t = blockIdx.x * blockDim.x + threadIdx.x;
    if (t < S_) {
        int e = g_eidx[t];
        int pos = atomicAdd(&g_cur[e], 1);
        g_rows[pos] = t >> 1;
        g_slot[t] = pos;
    }
}

// -------- tiled fp32 GEMM: C[slot, n] = act(A[row(slot), k] * W_e[k, n] + bias_e[n]) --------
// grid: (N/128, 32, E).  BM=BN=128, BK=16, 256 threads, 8x8 per thread.
template <bool GATHER, bool RELU>
__global__ __launch_bounds__(256)
void k_gemm(const float* __restrict__ A, XPtrs xs,
            const float* __restrict__ W, const float* __restrict__ bias,
            float* __restrict__ C, int K, int N) {
    const int e   = blockIdx.z;
    const int off = g_off[e];
    const int cnt = g_off[e + 1] - off;
    const int m0  = blockIdx.y * 128;
    if (m0 >= cnt) return;
    const int n0  = blockIdx.x * 128;

    __shared__ float As[16][132];
    __shared__ float Bs[16][128];

    const int tid = threadIdx.x;
    const int mA = tid >> 1;           // 0..127
    const int kA = (tid & 1) * 8;      // 0 or 8
    const int kB = tid >> 4;           // 0..15
    const int nB = (tid & 15) * 8;     // 0..120

    const int rloc = m0 + mA;
    const bool avalid = rloc < cnt;
    const float* arow = A;  // dummy
    if (avalid) {
        int slot = off + rloc;
        if (GATHER) arow = xs.p[e] + (long)g_rows[slot] * K;
        else        arow = A + (long)slot * K;
    }
    const float* wbase = W + (long)e * K * N;

    const int ty = tid >> 4, tx = tid & 15;
    float c[8][8];
#pragma unroll
    for (int i = 0; i < 8; i++)
#pragma unroll
        for (int j = 0; j < 8; j++) c[i][j] = 0.f;

    for (int k0 = 0; k0 < K; k0 += 16) {
        float4 a0, a1;
        if (avalid) {
            a0 = *(const float4*)(arow + k0 + kA);
            a1 = *(const float4*)(arow + k0 + kA + 4);
        } else {
            a0 = make_float4(0.f, 0.f, 0.f, 0.f); a1 = a0;
        }
        As[kA + 0][mA] = a0.x; As[kA + 1][mA] = a0.y;
        As[kA + 2][mA] = a0.z; As[kA + 3][mA] = a0.w;
        As[kA + 4][mA] = a1.x; As[kA + 5][mA] = a1.y;
        As[kA + 6][mA] = a1.z; As[kA + 7][mA] = a1.w;

        const float* wrow = wbase + (long)(k0 + kB) * N + n0 + nB;
        *(float4*)(&Bs[kB][nB])     = *(const float4*)(wrow);
        *(float4*)(&Bs[kB][nB + 4]) = *(const float4*)(wrow + 4);
        __syncthreads();

#pragma unroll
        for (int kk = 0; kk < 16; kk++) {
            float a[8], bb[8];
#pragma unroll
            for (int i = 0; i < 8; i++) a[i] = As[kk][ty * 8 + i];
#pragma unroll
            for (int j = 0; j < 8; j++) bb[j] = Bs[kk][tx * 8 + j];
#pragma unroll
            for (int i = 0; i < 8; i++)
#pragma unroll
                for (int j = 0; j < 8; j++)
                    c[i][j] = fmaf(a[i], bb[j], c[i][j]);
        }
        __syncthreads();
    }

    const float* brow = bias + (long)e * N + n0 + tx * 8;
    float bv[8];
#pragma unroll
    for (int j = 0; j < 8; j++) bv[j] = brow[j];
#pragma unroll
    for (int i = 0; i < 8; i++) {
        int rl = m0 + ty * 8 + i;
        if (rl < cnt) {
            float* crow = C + (long)(off + rl) * N + n0 + tx * 8;
            float4 v0, v1;
            float t0 = c[i][0] + bv[0], t1 = c[i][1] + bv[1];
            float t2 = c[i][2] + bv[2], t3 = c[i][3] + bv[3];
            float t4 = c[i][4] + bv[4], t5 = c[i][5] + bv[5];
            float t6 = c[i][6] + bv[6], t7 = c[i][7] + bv[7];
            if (RELU) {
                t0 = fmaxf(t0, 0.f); t1 = fmaxf(t1, 0.f); t2 = fmaxf(t2, 0.f); t3 = fmaxf(t3, 0.f);
                t4 = fmaxf(t4, 0.f); t5 = fmaxf(t5, 0.f); t6 = fmaxf(t6, 0.f); t7 = fmaxf(t7, 0.f);
            }
            v0.x = t0; v0.y = t1; v0.z = t2; v0.w = t3;
            v1.x = t4; v1.y = t5; v1.z = t6; v1.w = t7;
            *(float4*)(crow)     = v0;
            *(float4*)(crow + 4) = v1;
        }
    }
}

// -------- combine: out[b,:] = w0*eo[slot0,:] + w1*eo[slot1,:] --------
__global__ void k_combine(float* __restrict__ out) {
    int idx = blockIdx.x * 256 + threadIdx.x;     // over B*O/4 float4s
    int b  = idx >> 8;                            // 256 float4 per row
    int o4 = idx & 255;
    float w0 = g_wt[2 * b], w1 = g_wt[2 * b + 1];
    const float4* r0 = (const float4*)(g_eo + (long)g_slot[2 * b] * O_);
    const float4* r1 = (const float4*)(g_eo + (long)g_slot[2 * b + 1] * O_);
    float4 a = r0[o4], c = r1[o4], v;
    v.x = w0 * a.x + w1 * c.x;
    v.y = w0 * a.y + w1 * c.y;
    v.z = w0 * a.z + w1 * c.z;
    v.w = w0 * a.w + w1 * c.w;
    ((float4*)out)[idx] = v;
}

extern "C" void kernel_launch(void* const* d_in, const int* in_sizes, int n_in,
                              void* d_out, int out_size) {
    XPtrs xs;
    for (int i = 0; i < E_; i++) xs.p[i] = (const float*)d_in[i];
    const float* gw    = (const float*)d_in[8];
    const float* gb    = (const float*)d_in[9];
    const float* w_in  = (const float*)d_in[10];
    const float* b_in  = (const float*)d_in[11];
    const float* w_h   = (const float*)d_in[12];
    const float* b_h   = (const float*)d_in[13];
    const float* w_out = (const float*)d_in[14];
    const float* b_out = (const float*)d_in[15];
    float* out = (float*)d_out;

    float *h1, *h2, *eo;
    cudaGetSymbolAddress((void**)&h1, g_h1);
    cudaGetSymbolAddress((void**)&h2, g_h2);
    cudaGetSymbolAddress((void**)&eo, g_eo);

    k_zero<<<1, 32>>>();
    k_gate<<<B_, 256>>>(xs, gw, gb);
    k_scan<<<1, 32>>>();
    k_fill<<<S_ / 256, 256>>>();

    // layer 1: gathered x_e [cnt, 1024] x [1024, 2048] -> relu -> h1
    k_gemm<true, true><<<dim3(H_ / 128, B_ / 128, E_), 256>>>(
        nullptr, xs, w_in, b_in, h1, D_, H_);
    // layer 2: h1 [cnt, 2048] x [2048, 2048] -> relu -> h2
    k_gemm<false, true><<<dim3(H_ / 128, B_ / 128, E_), 256>>>(
        h1, xs, w_h, b_h, h2, H_, H_);
    // layer 3: h2 [cnt, 2048] x [2048, 1024] -> eo
    k_gemm<false, false><<<dim3(O_ / 128, B_ / 128, E_), 256>>>(
        h2, xs, w_out, b_out, eo, H_, O_);

    k_combine<<<(B_ * O_ / 4) / 256, 256>>>(out);
}

// round 4
// speedup vs baseline: 2.3542x; 2.3542x over previous
#include <cuda_runtime.h>
#include <cuda_bf16.h>
#include <math.h>
#include <stdint.h>

#define E_ 8
#define D_ 1024
#define H_ 2048
#define O_ 1024
#define B_ 4096
#define S_ 8192

// ---------------- scratch (device globals) ----------------
__device__ __align__(1024) __nv_bfloat16 g_xg_h[S_ * D_];
__device__ __align__(1024) __nv_bfloat16 g_xg_l[S_ * D_];
__device__ __align__(1024) __nv_bfloat16 g_h1_h[S_ * H_];
__device__ __align__(1024) __nv_bfloat16 g_h1_l[S_ * H_];
__device__ __align__(1024) __nv_bfloat16 g_h2_h[S_ * H_];
__device__ __align__(1024) __nv_bfloat16 g_h2_l[S_ * H_];
__device__ __align__(1024) __nv_bfloat16 g_win_h[E_ * H_ * D_];   // [e][n][k]
__device__ __align__(1024) __nv_bfloat16 g_win_l[E_ * H_ * D_];
__device__ __align__(1024) __nv_bfloat16 g_wh_h[E_ * H_ * H_];
__device__ __align__(1024) __nv_bfloat16 g_wh_l[E_ * H_ * H_];
__device__ __align__(1024) __nv_bfloat16 g_wo_h[E_ * O_ * H_];
__device__ __align__(1024) __nv_bfloat16 g_wo_l[E_ * O_ * H_];
__device__ __align__(16) float g_eo[S_ * O_];
__device__ int   g_rows[S_];
__device__ int   g_sexp[S_];
__device__ int   g_slot[S_];
__device__ int   g_eidx[S_];
__device__ float g_wt[S_];
__device__ int   g_cnt[E_];
__device__ int   g_off[E_ + 1];
__device__ int   g_cur[E_];

struct XPtrs { const float* p[E_]; };

// ---------------- small PTX wrappers (all baseline-family sm_80+) ----------------
__device__ __forceinline__ uint32_t smem_u32(const void* p) {
    uint32_t a;
    asm("{ .reg .u64 t; cvta.to.shared.u64 t, %1; cvt.u32.u64 %0, t; }" : "=r"(a) : "l"(p));
    return a;
}
__device__ __forceinline__ void cp16(uint32_t dst, const void* src) {
    asm volatile("cp.async.cg.shared.global [%0], [%1], 16;" :: "r"(dst), "l"(src));
}
#define CP_COMMIT() asm volatile("cp.async.commit_group;" ::: "memory")
#define CP_WAIT1()  asm volatile("cp.async.wait_group 1;" ::: "memory")

__device__ __forceinline__ void ldsm4(uint32_t* r, uint32_t addr) {
    asm volatile("ldmatrix.sync.aligned.m8n8.x4.shared.b16 {%0,%1,%2,%3}, [%4];"
        : "=r"(r[0]), "=r"(r[1]), "=r"(r[2]), "=r"(r[3]) : "r"(addr));
}
__device__ __forceinline__ void mma16816(float* c, const uint32_t* a, const uint32_t* b) {
    asm volatile("mma.sync.aligned.m16n8k16.row.col.f32.bf16.bf16.f32 "
        "{%0,%1,%2,%3}, {%4,%5,%6,%7}, {%8,%9}, {%0,%1,%2,%3};"
        : "+f"(c[0]), "+f"(c[1]), "+f"(c[2]), "+f"(c[3])
        : "r"(a[0]), "r"(a[1]), "r"(a[2]), "r"(a[3]), "r"(b[0]), "r"(b[1]));
}

// ---------------- gating / dispatch ----------------
__global__ void k_zero() { if (threadIdx.x < E_) g_cnt[threadIdx.x] = 0; }

__global__ void k_gate(XPtrs xs, const float* __restrict__ gw, const float* __restrict__ gb) {
    int b0 = blockIdx.x * 4;
    int tid = threadIdx.x;
    float acc[4][8];
#pragma unroll
    for (int t = 0; t < 4; t++)
#pragma unroll
        for (int e = 0; e < 8; e++) acc[t][e] = 0.f;
    for (int j = tid; j < E_ * D_; j += 256) {
        const float* xp = xs.p[j >> 10];
        int col = j & (D_ - 1);
        float4 w0 = *(const float4*)(gw + (long)j * 8);
        float4 w1 = *(const float4*)(gw + (long)j * 8 + 4);
#pragma unroll
        for (int t = 0; t < 4; t++) {
            float v = xp[(long)(b0 + t) * D_ + col];
            acc[t][0] = fmaf(v, w0.x, acc[t][0]); acc[t][1] = fmaf(v, w0.y, acc[t][1]);
            acc[t][2] = fmaf(v, w0.z, acc[t][2]); acc[t][3] = fmaf(v, w0.w, acc[t][3]);
            acc[t][4] = fmaf(v, w1.x, acc[t][4]); acc[t][5] = fmaf(v, w1.y, acc[t][5]);
            acc[t][6] = fmaf(v, w1.z, acc[t][6]); acc[t][7] = fmaf(v, w1.w, acc[t][7]);
        }
    }
#pragma unroll
    for (int o = 16; o > 0; o >>= 1)
#pragma unroll
        for (int t = 0; t < 4; t++)
#pragma unroll
            for (int e = 0; e < 8; e++)
                acc[t][e] += __shfl_down_sync(0xffffffffu, acc[t][e], o);
    __shared__ float s[8][4][8];
    int w = tid >> 5, lane = tid & 31;
    if (lane == 0)
#pragma unroll
        for (int t = 0; t < 4; t++)
#pragma unroll
            for (int e = 0; e < 8; e++) s[w][t][e] = acc[t][e];
    __syncthreads();
    if (tid < 4) {
        int t = tid, b = b0 + t;
        float lg[8];
#pragma unroll
        for (int e = 0; e < 8; e++) {
            float a = gb[e];
#pragma unroll
            for (int w2 = 0; w2 < 8; w2++) a += s[w2][t][e];
            lg[e] = a;
        }
        int i0 = 0;
        for (int e = 1; e < 8; e++) if (lg[e] > lg[i0]) i0 = e;
        int i1 = (i0 == 0) ? 1 : 0;
        for (int e = 0; e < 8; e++) if (e != i0 && lg[e] > lg[i1]) i1 = e;
        float ex = expf(lg[i1] - lg[i0]);
        float inv = 1.f / (1.f + ex);
        g_eidx[2 * b] = i0; g_eidx[2 * b + 1] = i1;
        g_wt[2 * b] = inv;  g_wt[2 * b + 1] = ex * inv;
        atomicAdd(&g_cnt[i0], 1);
        atomicAdd(&g_cnt[i1], 1);
    }
}

__global__ void k_scan() {
    if (threadIdx.x == 0) {
        int acc = 0;
        for (int e = 0; e < E_; e++) { g_off[e] = acc; g_cur[e] = acc; acc += g_cnt[e]; }
        g_off[E_] = acc;
    }
}

__global__ void k_fill() {
    int t = blockIdx.x * blockDim.x + threadIdx.x;
    if (t < S_) {
        int e = g_eidx[t];
        int pos = atomicAdd(&g_cur[e], 1);
        g_rows[pos] = t >> 1;
        g_sexp[pos] = e;
        g_slot[t] = pos;
    }
}

union U4 { __nv_bfloat16 b[4]; uint2 u; };

__global__ void k_gather(XPtrs xs) {
    int sIdx = blockIdx.x;
    int e = g_sexp[sIdx];
    long t = g_rows[sIdx];
    const float4* src = (const float4*)(xs.p[e] + t * D_);
    __nv_bfloat16* oh = g_xg_h + (long)sIdx * D_;
    __nv_bfloat16* ol = g_xg_l + (long)sIdx * D_;
    for (int i = threadIdx.x; i < D_ / 4; i += 128) {
        float4 v = src[i];
        U4 hv, lv;
        float vv[4] = {v.x, v.y, v.z, v.w};
#pragma unroll
        for (int j = 0; j < 4; j++) {
            __nv_bfloat16 h = __float2bfloat16(vv[j]);
            hv.b[j] = h;
            lv.b[j] = __float2bfloat16(vv[j] - __bfloat162float(h));
        }
        *(uint2*)(oh + i * 4) = hv.u;
        *(uint2*)(ol + i * 4) = lv.u;
    }
}

// transpose + split: W[e][k][n] fp32 -> Wt_hi/lo[e][n][k] bf16
__global__ void k_convw(const float* __restrict__ W, __nv_bfloat16* __restrict__ Th,
                        __nv_bfloat16* __restrict__ Tl, int K, int N) {
    __shared__ float t[32][33];
    int e = blockIdx.z;
    long base = (long)e * K * N;
    int n0 = blockIdx.x * 32, k0 = blockIdx.y * 32;
    int tx = threadIdx.x, ty = threadIdx.y;
#pragma unroll
    for (int i = 0; i < 32; i += 8)
        t[ty + i][tx] = W[base + (long)(k0 + ty + i) * N + n0 + tx];
    __syncthreads();
    long ob = (long)e * N * K;
#pragma unroll
    for (int i = 0; i < 32; i += 8) {
        float v = t[tx][ty + i];
        __nv_bfloat16 h = __float2bfloat16(v);
        long idx = ob + (long)(n0 + ty + i) * K + k0 + tx;
        Th[idx] = h;
        Tl[idx] = __float2bfloat16(v - __bfloat162float(h));
    }
}

// ---------------- HMMA GEMM (mma.sync bf16, bf16x3 split) ----------------
// C[slot, n] = act( sum_k A[slot,k]*W_e[n,k] + bias_e[n] )
// BM=128, BN=128, BK=32, 256 threads, warp tile 32x64.
// smem per stage: 4 tiles (Ah, Al, Bh, Bl), each 128 rows x 32 bf16, padded to
// 40 bf16/row (80 B, stride 20 words -> ldmatrix conflict-free). 40960 B/stage.
#define TILE_B16 5120          // 128*40
#define TILE_B   10240         // bytes
#define STAGE_B  40960

template <int K, int N, bool RELU, bool SPLIT>
__global__ void __launch_bounds__(256, 1) k_mma(
    const __nv_bfloat16* __restrict__ Ah, const __nv_bfloat16* __restrict__ Al,
    const __nv_bfloat16* __restrict__ Bh, const __nv_bfloat16* __restrict__ Bl,
    const float* __restrict__ bias,
    __nv_bfloat16* __restrict__ oh, __nv_bfloat16* __restrict__ ol,
    float* __restrict__ of) {
    const int e   = blockIdx.z;
    const int off = g_off[e];
    const int cnt = g_off[e + 1] - off;
    const int m0  = blockIdx.y * 128;
    if (m0 >= cnt) return;
    const int n0  = blockIdx.x * 128;
    const int arow0 = off + m0;

    extern __shared__ char smem[];
    __shared__ float sbias[128];
    const uint32_t sb = smem_u32(smem);

    const int tid = threadIdx.x, wid = tid >> 5, lane = tid & 31;
    if (tid < 128) sbias[tid] = bias[(long)e * N + n0 + tid];

    // ---- per-thread load plan: 8 x 16B chunks per stage ----
    const __nv_bfloat16* gsrc[8];
    uint32_t sdst[8];
#pragma unroll
    for (int i = 0; i < 8; i++) {
        int id = tid + i * 256;         // 0..2047
        int t = id >> 9;                // tile 0..3
        int rem = id & 511;
        int row = rem >> 2;
        int cq = rem & 3;
        const __nv_bfloat16* g;
        if (t < 2) {
            long r = arow0 + row;
            if (r > S_ - 1) r = S_ - 1;
            g = (t == 0 ? Ah : Al) + r * (long)K + cq * 8;
        } else {
            long r = (long)e * N + n0 + row;
            g = (t == 2 ? Bh : Bl) + r * (long)K + cq * 8;
        }
        gsrc[i] = g;
        sdst[i] = sb + t * TILE_B + (row * 40 + cq * 8) * 2;
    }

    // prologue: stages 0,1
#pragma unroll
    for (int i = 0; i < 8; i++) cp16(sdst[i], gsrc[i]);
    CP_COMMIT();
#pragma unroll
    for (int i = 0; i < 8; i++) cp16(sdst[i] + STAGE_B, gsrc[i] + 32);
    CP_COMMIT();

    // ---- warp tiling ----
    const int base_m = (wid & 3) * 32;
    const int base_n = (wid >> 2) * 64;
    const uint32_t arow = base_m + (lane & 15);
    const uint32_t acol = (lane >> 4) << 3;                       // +0/+8 in k
    const uint32_t brow = base_n + ((lane >> 4) << 3) + (lane & 7);
    const uint32_t bcol = ((lane >> 3) & 1) << 3;

    float acc[2][8][4];
#pragma unroll
    for (int mi = 0; mi < 2; mi++)
#pragma unroll
        for (int nj = 0; nj < 8; nj++)
#pragma unroll
            for (int q = 0; q < 4; q++) acc[mi][nj][q] = 0.f;

    const int NIT = K / 32;
#pragma unroll 1
    for (int it = 0; it < NIT; it++) {
        CP_WAIT1();
        __syncthreads();
        const uint32_t st = sb + (it & 1) * STAGE_B;
#pragma unroll
        for (int ks = 0; ks < 2; ks++) {
            uint32_t ah[2][4], al[2][4], bh[4][4], bl[4][4];
            uint32_t ab = st + (arow * 40 + ks * 16 + acol) * 2;
            ldsm4(ah[0], ab);
            ldsm4(ah[1], ab + 1280);
            ldsm4(al[0], ab + TILE_B);
            ldsm4(al[1], ab + TILE_B + 1280);
            uint32_t bb = st + 2 * TILE_B + (brow * 40 + ks * 16 + bcol) * 2;
#pragma unroll
            for (int ni = 0; ni < 4; ni++) {
                ldsm4(bh[ni], bb + ni * 1280);
                ldsm4(bl[ni], bb + TILE_B + ni * 1280);
            }
#pragma unroll
            for (int mi = 0; mi < 2; mi++)
#pragma unroll
                for (int ni = 0; ni < 4; ni++)
#pragma unroll
                    for (int h = 0; h < 2; h++) {
                        int nj = ni * 2 + h;
                        mma16816(acc[mi][nj], ah[mi], &bh[ni][h * 2]);
                        mma16816(acc[mi][nj], ah[mi], &bl[ni][h * 2]);
                        mma16816(acc[mi][nj], al[mi], &bh[ni][h * 2]);
                    }
        }
        __syncthreads();
        if (it + 2 < NIT) {
            const int k = (it + 2) * 32;
            const uint32_t so = (it & 1) * STAGE_B;
#pragma unroll
            for (int i = 0; i < 8; i++) cp16(sdst[i] + so, gsrc[i] + k);
        }
        CP_COMMIT();
    }

    // ---- epilogue ----
#pragma unroll
    for (int mi = 0; mi < 2; mi++) {
        int gr0 = m0 + base_m + mi * 16 + (lane >> 2);
        bool v0 = gr0 < cnt, v1 = (gr0 + 8) < cnt;
        long s0 = (long)(off + gr0), s1 = s0 + 8;
#pragma unroll
        for (int nj = 0; nj < 8; nj++) {
            int col = base_n + nj * 8 + (lane & 3) * 2;
            float2 bv = *(float2*)&sbias[col];
            float x0 = acc[mi][nj][0] + bv.x;
            float x1 = acc[mi][nj][1] + bv.y;
            float x2 = acc[mi][nj][2] + bv.x;
            float x3 = acc[mi][nj][3] + bv.y;
            if (RELU) {
                x0 = fmaxf(x0, 0.f); x1 = fmaxf(x1, 0.f);
                x2 = fmaxf(x2, 0.f); x3 = fmaxf(x3, 0.f);
            }
            long gcol = n0 + col;
            if (SPLIT) {
                if (v0) {
                    __nv_bfloat16 h0 = __float2bfloat16(x0), h1 = __float2bfloat16(x1);
                    __nv_bfloat162 hp; hp.x = h0; hp.y = h1;
                    __nv_bfloat162 lp;
                    lp.x = __float2bfloat16(x0 - __bfloat162float(h0));
                    lp.y = __float2bfloat16(x1 - __bfloat162float(h1));
                    *(__nv_bfloat162*)(oh + s0 * N + gcol) = hp;
                    *(__nv_bfloat162*)(ol + s0 * N + gcol) = lp;
                }
                if (v1) {
                    __nv_bfloat16 h2 = __float2bfloat16(x2), h3 = __float2bfloat16(x3);
                    __nv_bfloat162 hp; hp.x = h2; hp.y = h3;
                    __nv_bfloat162 lp;
                    lp.x = __float2bfloat16(x2 - __bfloat162float(h2));
                    lp.y = __float2bfloat16(x3 - __bfloat162float(h3));
                    *(__nv_bfloat162*)(oh + s1 * N + gcol) = hp;
                    *(__nv_bfloat162*)(ol + s1 * N + gcol) = lp;
                }
            } else {
                if (v0) { float2 v; v.x = x0; v.y = x1; *(float2*)(of + s0 * N + gcol) = v; }
                if (v1) { float2 v; v.x = x2; v.y = x3; *(float2*)(of + s1 * N + gcol) = v; }
            }
        }
    }
}

// ---------------- combine ----------------
__global__ void k_combine(float* __restrict__ out) {
    int idx = blockIdx.x * 256 + threadIdx.x;
    int b = idx >> 8;
    int o4 = idx & 255;
    float w0 = g_wt[2 * b], w1 = g_wt[2 * b + 1];
    const float4* r0 = (const float4*)(g_eo + (long)g_slot[2 * b] * O_);
    const float4* r1 = (const float4*)(g_eo + (long)g_slot[2 * b + 1] * O_);
    float4 a = r0[o4], c = r1[o4], v;
    v.x = w0 * a.x + w1 * c.x;
    v.y = w0 * a.y + w1 * c.y;
    v.z = w0 * a.z + w1 * c.z;
    v.w = w0 * a.w + w1 * c.w;
    ((float4*)out)[idx] = v;
}

// ---------------- host ----------------
#define SMEM_DYN (2 * STAGE_B)

extern "C" void kernel_launch(void* const* d_in, const int* in_sizes, int n_in,
                              void* d_out, int out_size) {
    XPtrs xs;
    for (int i = 0; i < E_; i++) xs.p[i] = (const float*)d_in[i];
    const float* gw    = (const float*)d_in[8];
    const float* gb    = (const float*)d_in[9];
    const float* w_in  = (const float*)d_in[10];
    const float* b_in  = (const float*)d_in[11];
    const float* w_h   = (const float*)d_in[12];
    const float* b_h   = (const float*)d_in[13];
    const float* w_out = (const float*)d_in[14];
    const float* b_out = (const float*)d_in[15];
    float* out = (float*)d_out;

    void *xg_h, *xg_l, *h1_h, *h1_l, *h2_h, *h2_l;
    void *win_h, *win_l, *wh_h, *wh_l, *wo_h, *wo_l, *eo;
    cudaGetSymbolAddress(&xg_h, g_xg_h);   cudaGetSymbolAddress(&xg_l, g_xg_l);
    cudaGetSymbolAddress(&h1_h, g_h1_h);   cudaGetSymbolAddress(&h1_l, g_h1_l);
    cudaGetSymbolAddress(&h2_h, g_h2_h);   cudaGetSymbolAddress(&h2_l, g_h2_l);
    cudaGetSymbolAddress(&win_h, g_win_h); cudaGetSymbolAddress(&win_l, g_win_l);
    cudaGetSymbolAddress(&wh_h, g_wh_h);   cudaGetSymbolAddress(&wh_l, g_wh_l);
    cudaGetSymbolAddress(&wo_h, g_wo_h);   cudaGetSymbolAddress(&wo_l, g_wo_l);
    cudaGetSymbolAddress(&eo, g_eo);

    cudaFuncSetAttribute((const void*)k_mma<1024, 2048, true, true>,
                         cudaFuncAttributeMaxDynamicSharedMemorySize, SMEM_DYN);
    cudaFuncSetAttribute((const void*)k_mma<2048, 2048, true, true>,
                         cudaFuncAttributeMaxDynamicSharedMemorySize, SMEM_DYN);
    cudaFuncSetAttribute((const void*)k_mma<2048, 1024, false, false>,
                         cudaFuncAttributeMaxDynamicSharedMemorySize, SMEM_DYN);

    k_zero<<<1, 32>>>();
    k_gate<<<B_ / 4, 256>>>(xs, gw, gb);
    k_scan<<<1, 32>>>();
    k_fill<<<S_ / 256, 256>>>();
    k_gather<<<S_, 128>>>(xs);
    k_convw<<<dim3(H_ / 32, D_ / 32, E_), dim3(32, 8)>>>(w_in, (__nv_bfloat16*)win_h,
                                                         (__nv_bfloat16*)win_l, D_, H_);
    k_convw<<<dim3(H_ / 32, H_ / 32, E_), dim3(32, 8)>>>(w_h, (__nv_bfloat16*)wh_h,
                                                         (__nv_bfloat16*)wh_l, H_, H_);
    k_convw<<<dim3(O_ / 32, H_ / 32, E_), dim3(32, 8)>>>(w_out, (__nv_bfloat16*)wo_h,
                                                         (__nv_bfloat16*)wo_l, H_, O_);

    // worst-case per-expert rows = S_ -> grid.y = 64 (inactive blocks early-exit)
    k_mma<1024, 2048, true, true><<<dim3(H_ / 128, S_ / 128, E_), 256, SMEM_DYN>>>(
        (const __nv_bfloat16*)xg_h, (const __nv_bfloat16*)xg_l,
        (const __nv_bfloat16*)win_h, (const __nv_bfloat16*)win_l,
        b_in, (__nv_bfloat16*)h1_h, (__nv_bfloat16*)h1_l, nullptr);
    k_mma<2048, 2048, true, true><<<dim3(H_ / 128, S_ / 128, E_), 256, SMEM_DYN>>>(
        (const __nv_bfloat16*)h1_h, (const __nv_bfloat16*)h1_l,
        (const __nv_bfloat16*)wh_h, (const __nv_bfloat16*)wh_l,
        b_h, (__nv_bfloat16*)h2_h, (__nv_bfloat16*)h2_l, nullptr);
    k_mma<2048, 1024, false, false><<<dim3(O_ / 128, S_ / 128, E_), 256, SMEM_DYN>>>(
        (const __nv_bfloat16*)h2_h, (const __nv_bfloat16*)h2_l,
        (const __nv_bfloat16*)wo_h, (const __nv_bfloat16*)wo_l,
        b_out, nullptr, nullptr, (float*)eo);

    k_combine<<<(B_ * O_ / 4) / 256, 256>>>(out);
}

// round 6
// speedup vs baseline: 2.4288x; 1.0317x over previous
#include <cuda_runtime.h>
#include <cuda_bf16.h>
#include <math.h>
#include <stdint.h>

#define E_ 8
#define D_ 1024
#define H_ 2048
#define O_ 1024
#define B_ 4096
#define S_ 8192

// ---------------- scratch (device globals) ----------------
__device__ __align__(1024) __nv_bfloat16 g_xg_h[S_ * D_];
__device__ __align__(1024) __nv_bfloat16 g_xg_l[S_ * D_];
__device__ __align__(1024) __nv_bfloat16 g_h1_h[S_ * H_];
__device__ __align__(1024) __nv_bfloat16 g_h1_l[S_ * H_];
__device__ __align__(1024) __nv_bfloat16 g_h2_h[S_ * H_];
__device__ __align__(1024) __nv_bfloat16 g_h2_l[S_ * H_];
__device__ __align__(1024) __nv_bfloat16 g_win_h[E_ * H_ * D_];   // [e][n][k]
__device__ __align__(1024) __nv_bfloat16 g_win_l[E_ * H_ * D_];
__device__ __align__(1024) __nv_bfloat16 g_wh_h[E_ * H_ * H_];
__device__ __align__(1024) __nv_bfloat16 g_wh_l[E_ * H_ * H_];
__device__ __align__(1024) __nv_bfloat16 g_wo_h[E_ * O_ * H_];
__device__ __align__(1024) __nv_bfloat16 g_wo_l[E_ * O_ * H_];
__device__ __align__(16) float g_eo[S_ * O_];
__device__ int   g_rows[S_];
__device__ int   g_sexp[S_];
__device__ int   g_slot[S_];
__device__ int   g_eidx[S_];
__device__ float g_wt[S_];
__device__ int   g_cnt[E_];
__device__ int   g_off[E_ + 1];
__device__ int   g_cur[E_];

struct XPtrs { const float* p[E_]; };

// ---------------- PTX wrappers (baseline-family sm_80+) ----------------
__device__ __forceinline__ uint32_t smem_u32(const void* p) {
    uint32_t a;
    asm("{ .reg .u64 t; cvta.to.shared.u64 t, %1; cvt.u32.u64 %0, t; }" : "=r"(a) : "l"(p));
    return a;
}
__device__ __forceinline__ void cp16(uint32_t dst, const void* src) {
    asm volatile("cp.async.cg.shared.global [%0], [%1], 16;" :: "r"(dst), "l"(src));
}
#define CP_COMMIT() asm volatile("cp.async.commit_group;" ::: "memory")
#define CP_WAIT1()  asm volatile("cp.async.wait_group 1;" ::: "memory")

__device__ __forceinline__ void ldsm4(uint32_t* r, uint32_t addr) {
    asm volatile("ldmatrix.sync.aligned.m8n8.x4.shared.b16 {%0,%1,%2,%3}, [%4];"
        : "=r"(r[0]), "=r"(r[1]), "=r"(r[2]), "=r"(r[3]) : "r"(addr));
}
__device__ __forceinline__ void mma16816(float* c, const uint32_t* a, const uint32_t* b) {
    asm volatile("mma.sync.aligned.m16n8k16.row.col.f32.bf16.bf16.f32 "
        "{%0,%1,%2,%3}, {%4,%5,%6,%7}, {%8,%9}, {%0,%1,%2,%3};"
        : "+f"(c[0]), "+f"(c[1]), "+f"(c[2]), "+f"(c[3])
        : "r"(a[0]), "r"(a[1]), "r"(a[2]), "r"(a[3]), "r"(b[0]), "r"(b[1]));
}

// ---------------- gating / dispatch ----------------
__global__ void k_zero() { if (threadIdx.x < E_) g_cnt[threadIdx.x] = 0; }

__global__ void k_gate(XPtrs xs, const float* __restrict__ gw, const float* __restrict__ gb) {
    int b0 = blockIdx.x * 4;
    int tid = threadIdx.x;
    float acc[4][8];
#pragma unroll
    for (int t = 0; t < 4; t++)
#pragma unroll
        for (int e = 0; e < 8; e++) acc[t][e] = 0.f;
    for (int j = tid; j < E_ * D_; j += 256) {
        const float* xp = xs.p[j >> 10];
        int col = j & (D_ - 1);
        float4 w0 = *(const float4*)(gw + (long)j * 8);
        float4 w1 = *(const float4*)(gw + (long)j * 8 + 4);
#pragma unroll
        for (int t = 0; t < 4; t++) {
            float v = xp[(long)(b0 + t) * D_ + col];
            acc[t][0] = fmaf(v, w0.x, acc[t][0]); acc[t][1] = fmaf(v, w0.y, acc[t][1]);
            acc[t][2] = fmaf(v, w0.z, acc[t][2]); acc[t][3] = fmaf(v, w0.w, acc[t][3]);
            acc[t][4] = fmaf(v, w1.x, acc[t][4]); acc[t][5] = fmaf(v, w1.y, acc[t][5]);
            acc[t][6] = fmaf(v, w1.z, acc[t][6]); acc[t][7] = fmaf(v, w1.w, acc[t][7]);
        }
    }
#pragma unroll
    for (int o = 16; o > 0; o >>= 1)
#pragma unroll
        for (int t = 0; t < 4; t++)
#pragma unroll
            for (int e = 0; e < 8; e++)
                acc[t][e] += __shfl_down_sync(0xffffffffu, acc[t][e], o);
    __shared__ float s[8][4][8];
    int w = tid >> 5, lane = tid & 31;
    if (lane == 0)
#pragma unroll
        for (int t = 0; t < 4; t++)
#pragma unroll
            for (int e = 0; e < 8; e++) s[w][t][e] = acc[t][e];
    __syncthreads();
    if (tid < 4) {
        int t = tid, b = b0 + t;
        float lg[8];
#pragma unroll
        for (int e = 0; e < 8; e++) {
            float a = gb[e];
#pragma unroll
            for (int w2 = 0; w2 < 8; w2++) a += s[w2][t][e];
            lg[e] = a;
        }
        int i0 = 0;
        for (int e = 1; e < 8; e++) if (lg[e] > lg[i0]) i0 = e;
        int i1 = (i0 == 0) ? 1 : 0;
        for (int e = 0; e < 8; e++) if (e != i0 && lg[e] > lg[i1]) i1 = e;
        float ex = expf(lg[i1] - lg[i0]);
        float inv = 1.f / (1.f + ex);
        g_eidx[2 * b] = i0; g_eidx[2 * b + 1] = i1;
        g_wt[2 * b] = inv;  g_wt[2 * b + 1] = ex * inv;
        atomicAdd(&g_cnt[i0], 1);
        atomicAdd(&g_cnt[i1], 1);
    }
}

__global__ void k_scan() {
    if (threadIdx.x == 0) {
        int acc = 0;
        for (int e = 0; e < E_; e++) { g_off[e] = acc; g_cur[e] = acc; acc += g_cnt[e]; }
        g_off[E_] = acc;
    }
}

__global__ void k_fill() {
    int t = blockIdx.x * blockDim.x + threadIdx.x;
    if (t < S_) {
        int e = g_eidx[t];
        int pos = atomicAdd(&g_cur[e], 1);
        g_rows[pos] = t >> 1;
        g_sexp[pos] = e;
        g_slot[t] = pos;
    }
}

union U4 { __nv_bfloat16 b[4]; uint2 u; };

__global__ void k_gather(XPtrs xs) {
    int sIdx = blockIdx.x;
    int e = g_sexp[sIdx];
    long t = g_rows[sIdx];
    const float4* src = (const float4*)(xs.p[e] + t * D_);
    __nv_bfloat16* oh = g_xg_h + (long)sIdx * D_;
    __nv_bfloat16* ol = g_xg_l + (long)sIdx * D_;
    for (int i = threadIdx.x; i < D_ / 4; i += 128) {
        float4 v = src[i];
        U4 hv, lv;
        float vv[4] = {v.x, v.y, v.z, v.w};
#pragma unroll
        for (int j = 0; j < 4; j++) {
            __nv_bfloat16 h = __float2bfloat16(vv[j]);
            hv.b[j] = h;
            lv.b[j] = __float2bfloat16(vv[j] - __bfloat162float(h));
        }
        *(uint2*)(oh + i * 4) = hv.u;
        *(uint2*)(ol + i * 4) = lv.u;
    }
}

// transpose + split: W[e][k][n] fp32 -> Wt_hi/lo[e][n][k] bf16
__global__ void k_convw(const float* __restrict__ W, __nv_bfloat16* __restrict__ Th,
                        __nv_bfloat16* __restrict__ Tl, int K, int N) {
    __shared__ float t[32][33];
    int e = blockIdx.z;
    long base = (long)e * K * N;
    int n0 = blockIdx.x * 32, k0 = blockIdx.y * 32;
    int tx = threadIdx.x, ty = threadIdx.y;
#pragma unroll
    for (int i = 0; i < 32; i += 8)
        t[ty + i][tx] = W[base + (long)(k0 + ty + i) * N + n0 + tx];
    __syncthreads();
    long ob = (long)e * N * K;
#pragma unroll
    for (int i = 0; i < 32; i += 8) {
        float v = t[tx][ty + i];
        __nv_bfloat16 h = __float2bfloat16(v);
        long idx = ob + (long)(n0 + ty + i) * K + k0 + tx;
        Th[idx] = h;
        Tl[idx] = __float2bfloat16(v - __bfloat162float(h));
    }
}

// ---------------- HMMA GEMM (mma.sync bf16, bf16x3 split) ----------------
// BM=128, BN=256, BK=32, 256 threads (8 warps = 2m x 4n), warp tile 64x64.
// smem stage: Ah(10240) Al(10240) Bh(20480) Bl(20480) = 61440 B, pitch 40 bf16.
#define AT_B 10240
#define BT_B 20480
#define ST_B 61440

template <int K, int N, bool RELU, bool SPLIT>
__global__ void __launch_bounds__(256, 1) k_mma(
    const __nv_bfloat16* __restrict__ Ah, const __nv_bfloat16* __restrict__ Al,
    const __nv_bfloat16* __restrict__ Bh, const __nv_bfloat16* __restrict__ Bl,
    const float* __restrict__ bias,
    __nv_bfloat16* __restrict__ oh, __nv_bfloat16* __restrict__ ol,
    float* __restrict__ of) {
    const int e   = blockIdx.z;
    const int off = g_off[e];
    const int cnt = g_off[e + 1] - off;
    const int m0  = blockIdx.y * 128;
    if (m0 >= cnt) return;
    const int n0  = blockIdx.x * 256;
    const int arow0 = off + m0;

    extern __shared__ char smem[];
    __shared__ float sbias[256];
    const uint32_t sb = smem_u32(smem);

    const int tid = threadIdx.x, wid = tid >> 5, lane = tid & 31;
    sbias[tid] = bias[(long)e * N + n0 + tid];

    // ---- load plan: rA = tid>>2 (0..63), cq = tid&3 ----
    const int rA = tid >> 2, cq = tid & 3;
    long r0 = arow0 + rA;      if (r0 > S_ - 1) r0 = S_ - 1;
    long r1 = arow0 + rA + 64; if (r1 > S_ - 1) r1 = S_ - 1;
    const __nv_bfloat16* aH0 = Ah + r0 * (long)K + cq * 8;
    const __nv_bfloat16* aH1 = Ah + r1 * (long)K + cq * 8;
    const __nv_bfloat16* aL0 = Al + r0 * (long)K + cq * 8;
    const __nv_bfloat16* aL1 = Al + r1 * (long)K + cq * 8;
    const __nv_bfloat16* bH = Bh + ((long)e * N + n0 + rA) * (long)K + cq * 8;
    const __nv_bfloat16* bL = Bl + ((long)e * N + n0 + rA) * (long)K + cq * 8;
    const long bstep = 64L * K;
    const uint32_t sA = sb + rA * 80 + cq * 16;
    const uint32_t sB = sb + 2 * AT_B + rA * 80 + cq * 16;

#define LOAD_STAGE(soff, koff) do {                                   \
    cp16(sA + (soff),                aH0 + (koff));                   \
    cp16(sA + (soff) + 64 * 80,      aH1 + (koff));                   \
    cp16(sA + (soff) + AT_B,         aL0 + (koff));                   \
    cp16(sA + (soff) + AT_B + 64*80, aL1 + (koff));                   \
    _Pragma("unroll")                                                 \
    for (int j = 0; j < 4; j++) {                                     \
        cp16(sB + (soff) + j * 64 * 80,        bH + (koff) + j * bstep); \
        cp16(sB + (soff) + BT_B + j * 64 * 80, bL + (koff) + j * bstep); \
    }                                                                 \
} while (0)

    LOAD_STAGE(0, 0);
    CP_COMMIT();
    LOAD_STAGE(ST_B, 32);
    CP_COMMIT();

    // ---- warp tiling: 2m x 4n, warp tile 64x64 ----
    const int base_m = (wid & 1) * 64;
    const int base_n = (wid >> 1) * 64;
    const uint32_t arow = base_m + (lane & 15);
    const uint32_t acol = (lane >> 4) << 3;
    const uint32_t brow = base_n + ((lane >> 4) << 3) + (lane & 7);
    const uint32_t bcol = ((lane >> 3) & 1) << 3;

    float acc[4][8][4];
#pragma unroll
    for (int mi = 0; mi < 4; mi++)
#pragma unroll
        for (int nj = 0; nj < 8; nj++)
#pragma unroll
            for (int q = 0; q < 4; q++) acc[mi][nj][q] = 0.f;

    const int NIT = K / 32;
#pragma unroll 1
    for (int it = 0; it < NIT; it++) {
        CP_WAIT1();
        __syncthreads();
        const uint32_t st = sb + (it & 1) * ST_B;
#pragma unroll
        for (int ks = 0; ks < 2; ks++) {
            uint32_t ah[4][4], al[4][4], bh[4][4], bl[4][4];
            uint32_t ab = st + (arow * 40 + ks * 16 + acol) * 2;
            uint32_t bb = st + 2 * AT_B + (brow * 40 + ks * 16 + bcol) * 2;
#pragma unroll
            for (int mi = 0; mi < 4; mi++) {
                ldsm4(ah[mi], ab + mi * 1280);
                ldsm4(al[mi], ab + AT_B + mi * 1280);
            }
#pragma unroll
            for (int ni = 0; ni < 4; ni++) {
                ldsm4(bh[ni], bb + ni * 1280);
                ldsm4(bl[ni], bb + BT_B + ni * 1280);
            }
#pragma unroll
            for (int mi = 0; mi < 4; mi++)
#pragma unroll
                for (int ni = 0; ni < 4; ni++)
#pragma unroll
                    for (int h = 0; h < 2; h++) {
                        int nj = ni * 2 + h;
                        mma16816(acc[mi][nj], ah[mi], &bh[ni][h * 2]);
                        mma16816(acc[mi][nj], ah[mi], &bl[ni][h * 2]);
                        mma16816(acc[mi][nj], al[mi], &bh[ni][h * 2]);
                    }
        }
        __syncthreads();
        if (it + 2 < NIT) {
            const int k = (it + 2) * 32;
            const uint32_t so = (it & 1) * ST_B;
            LOAD_STAGE(so, k);
        }
        CP_COMMIT();
    }
#undef LOAD_STAGE

    // ---- epilogue ----
#pragma unroll
    for (int mi = 0; mi < 4; mi++) {
        int gr0 = m0 + base_m + mi * 16 + (lane >> 2);
        bool v0 = gr0 < cnt, v1 = (gr0 + 8) < cnt;
        long s0 = (long)(off + gr0), s1 = s0 + 8;
#pragma unroll
        for (int nj = 0; nj < 8; nj++) {
            int col = base_n + nj * 8 + (lane & 3) * 2;
            float2 bv = *(float2*)&sbias[col];
            float x0 = acc[mi][nj][0] + bv.x;
            float x1 = acc[mi][nj][1] + bv.y;
            float x2 = acc[mi][nj][2] + bv.x;
            float x3 = acc[mi][nj][3] + bv.y;
            if (RELU) {
                x0 = fmaxf(x0, 0.f); x1 = fmaxf(x1, 0.f);
                x2 = fmaxf(x2, 0.f); x3 = fmaxf(x3, 0.f);
            }
            long gcol = n0 + col;
            if (SPLIT) {
                if (v0) {
                    __nv_bfloat16 h0 = __float2bfloat16(x0), h1 = __float2bfloat16(x1);
                    __nv_bfloat162 hp; hp.x = h0; hp.y = h1;
                    __nv_bfloat162 lp;
                    lp.x = __float2bfloat16(x0 - __bfloat162float(h0));
                    lp.y = __float2bfloat16(x1 - __bfloat162float(h1));
                    *(__nv_bfloat162*)(oh + s0 * N + gcol) = hp;
                    *(__nv_bfloat162*)(ol + s0 * N + gcol) = lp;
                }
                if (v1) {
                    __nv_bfloat16 h2 = __float2bfloat16(x2), h3 = __float2bfloat16(x3);
                    __nv_bfloat162 hp; hp.x = h2; hp.y = h3;
                    __nv_bfloat162 lp;
                    lp.x = __float2bfloat16(x2 - __bfloat162float(h2));
                    lp.y = __float2bfloat16(x3 - __bfloat162float(h3));
                    *(__nv_bfloat162*)(oh + s1 * N + gcol) = hp;
                    *(__nv_bfloat162*)(ol + s1 * N + gcol) = lp;
                }
            } else {
                if (v0) { float2 v; v.x = x0; v.y = x1; *(float2*)(of + s0 * N + gcol) = v; }
                if (v1) { float2 v; v.x = x2; v.y = x3; *(float2*)(of + s1 * N + gcol) = v; }
            }
        }
    }
}

// ---------------- combine ----------------
__global__ void k_combine(float* __restrict__ out) {
    int idx = blockIdx.x * 256 + threadIdx.x;
    int b = idx >> 8;
    int o4 = idx & 255;
    float w0 = g_wt[2 * b], w1 = g_wt[2 * b + 1];
    const float4* r0 = (const float4*)(g_eo + (long)g_slot[2 * b] * O_);
    const float4* r1 = (const float4*)(g_eo + (long)g_slot[2 * b + 1] * O_);
    float4 a = r0[o4], c = r1[o4], v;
    v.x = w0 * a.x + w1 * c.x;
    v.y = w0 * a.y + w1 * c.y;
    v.z = w0 * a.z + w1 * c.z;
    v.w = w0 * a.w + w1 * c.w;
    ((float4*)out)[idx] = v;
}

// ---------------- host ----------------
#define SMEM_DYN (2 * ST_B)

extern "C" void kernel_launch(void* const* d_in, const int* in_sizes, int n_in,
                              void* d_out, int out_size) {
    XPtrs xs;
    for (int i = 0; i < E_; i++) xs.p[i] = (const float*)d_in[i];
    const float* gw    = (const float*)d_in[8];
    const float* gb    = (const float*)d_in[9];
    const float* w_in  = (const float*)d_in[10];
    const float* b_in  = (const float*)d_in[11];
    const float* w_h   = (const float*)d_in[12];
    const float* b_h   = (const float*)d_in[13];
    const float* w_out = (const float*)d_in[14];
    const float* b_out = (const float*)d_in[15];
    float* out = (float*)d_out;

    void *xg_h, *xg_l, *h1_h, *h1_l, *h2_h, *h2_l;
    void *win_h, *win_l, *wh_h, *wh_l, *wo_h, *wo_l, *eo;
    cudaGetSymbolAddress(&xg_h, g_xg_h);   cudaGetSymbolAddress(&xg_l, g_xg_l);
    cudaGetSymbolAddress(&h1_h, g_h1_h);   cudaGetSymbolAddress(&h1_l, g_h1_l);
    cudaGetSymbolAddress(&h2_h, g_h2_h);   cudaGetSymbolAddress(&h2_l, g_h2_l);
    cudaGetSymbolAddress(&win_h, g_win_h); cudaGetSymbolAddress(&win_l, g_win_l);
    cudaGetSymbolAddress(&wh_h, g_wh_h);   cudaGetSymbolAddress(&wh_l, g_wh_l);
    cudaGetSymbolAddress(&wo_h, g_wo_h);   cudaGetSymbolAddress(&wo_l, g_wo_l);
    cudaGetSymbolAddress(&eo, g_eo);

    cudaFuncSetAttribute((const void*)k_mma<1024, 2048, true, true>,
                         cudaFuncAttributeMaxDynamicSharedMemorySize, SMEM_DYN);
    cudaFuncSetAttribute((const void*)k_mma<2048, 2048, true, true>,
                         cudaFuncAttributeMaxDynamicSharedMemorySize, SMEM_DYN);
    cudaFuncSetAttribute((const void*)k_mma<2048, 1024, false, false>,
                         cudaFuncAttributeMaxDynamicSharedMemorySize, SMEM_DYN);

    k_zero<<<1, 32>>>();
    k_gate<<<B_ / 4, 256>>>(xs, gw, gb);
    k_scan<<<1, 32>>>();
    k_fill<<<S_ / 256, 256>>>();
    k_gather<<<S_, 128>>>(xs);
    k_convw<<<dim3(H_ / 32, D_ / 32, E_), dim3(32, 8)>>>(w_in, (__nv_bfloat16*)win_h,
                                                         (__nv_bfloat16*)win_l, D_, H_);
    k_convw<<<dim3(H_ / 32, H_ / 32, E_), dim3(32, 8)>>>(w_h, (__nv_bfloat16*)wh_h,
                                                         (__nv_bfloat16*)wh_l, H_, H_);
    k_convw<<<dim3(O_ / 32, H_ / 32, E_), dim3(32, 8)>>>(w_out, (__nv_bfloat16*)wo_h,
                                                         (__nv_bfloat16*)wo_l, H_, O_);

    k_mma<1024, 2048, true, true><<<dim3(H_ / 256, S_ / 128, E_), 256, SMEM_DYN>>>(
        (const __nv_bfloat16*)xg_h, (const __nv_bfloat16*)xg_l,
        (const __nv_bfloat16*)win_h, (const __nv_bfloat16*)win_l,
        b_in, (__nv_bfloat16*)h1_h, (__nv_bfloat16*)h1_l, nullptr);
    k_mma<2048, 2048, true, true><<<dim3(H_ / 256, S_ / 128, E_), 256, SMEM_DYN>>>(
        (const __nv_bfloat16*)h1_h, (const __nv_bfloat16*)h1_l,
        (const __nv_bfloat16*)wh_h, (const __nv_bfloat16*)wh_l,
        b_h, (__nv_bfloat16*)h2_h, (__nv_bfloat16*)h2_l, nullptr);
    k_mma<2048, 1024, false, false><<<dim3(O_ / 256, S_ / 128, E_), 256, SMEM_DYN>>>(
        (const __nv_bfloat16*)h2_h, (const __nv_bfloat16*)h2_l,
        (const __nv_bfloat16*)wo_h, (const __nv_bfloat16*)wo_l,
        b_out, nullptr, nullptr, (float*)eo);

    k_combine<<<(B_ * O_ / 4) / 256, 256>>>(out);
}

// round 11
// speedup vs baseline: 5.6241x; 2.3155x over previous
#include <cuda_runtime.h>
#include <cuda_fp16.h>
#include <math.h>
#include <stdint.h>

#define E_ 8
#define D_ 1024
#define H_ 2048
#define O_ 1024
#define B_ 4096
#define S_ 8192

// ---------------- scratch (device globals) ----------------
__device__ __align__(1024) __half g_xg[S_ * D_];
__device__ __align__(1024) __half g_h1[S_ * H_];
__device__ __align__(1024) __half g_h2[S_ * H_];
__device__ __align__(1024) __half g_win[E_ * H_ * D_];   // [e][n][k]
__device__ __align__(1024) __half g_wh[E_ * H_ * H_];
__device__ __align__(1024) __half g_wo[E_ * O_ * H_];
__device__ __align__(16) float g_eo[S_ * O_];
__device__ int   g_rows[S_];
__device__ int   g_sexp[S_];
__device__ int   g_slot[S_];
__device__ int   g_eidx[S_];
__device__ float g_wt[S_];
__device__ int   g_cnt[E_];
__device__ int   g_off[E_ + 1];
__device__ int   g_cur[E_];

struct XPtrs { const float* p[E_]; };

// ---------------- PTX wrappers (baseline-family sm_80+) ----------------
__device__ __forceinline__ uint32_t smem_u32(const void* p) {
    uint32_t a;
    asm("{ .reg .u64 t; cvta.to.shared.u64 t, %1; cvt.u32.u64 %0, t; }" : "=r"(a) : "l"(p));
    return a;
}
__device__ __forceinline__ void cp16(uint32_t dst, const void* src) {
    asm volatile("cp.async.cg.shared.global [%0], [%1], 16;" :: "r"(dst), "l"(src));
}
#define CP_COMMIT() asm volatile("cp.async.commit_group;" ::: "memory")
#define CP_WAIT2()  asm volatile("cp.async.wait_group 2;" ::: "memory")

__device__ __forceinline__ void ldsm4(uint32_t* r, uint32_t addr) {
    asm volatile("ldmatrix.sync.aligned.m8n8.x4.shared.b16 {%0,%1,%2,%3}, [%4];"
        : "=r"(r[0]), "=r"(r[1]), "=r"(r[2]), "=r"(r[3]) : "r"(addr));
}
__device__ __forceinline__ void mma16816(float* c, const uint32_t* a, const uint32_t* b) {
    asm volatile("mma.sync.aligned.m16n8k16.row.col.f32.f16.f16.f32 "
        "{%0,%1,%2,%3}, {%4,%5,%6,%7}, {%8,%9}, {%0,%1,%2,%3};"
        : "+f"(c[0]), "+f"(c[1]), "+f"(c[2]), "+f"(c[3])
        : "r"(a[0]), "r"(a[1]), "r"(a[2]), "r"(a[3]), "r"(b[0]), "r"(b[1]));
}

// ---------------- gating / dispatch ----------------
__global__ void k_zero() { if (threadIdx.x < E_) g_cnt[threadIdx.x] = 0; }

__global__ void k_gate(XPtrs xs, const float* __restrict__ gw, const float* __restrict__ gb) {
    int b0 = blockIdx.x * 4;
    int tid = threadIdx.x;
    float acc[4][8];
#pragma unroll
    for (int t = 0; t < 4; t++)
#pragma unroll
        for (int e = 0; e < 8; e++) acc[t][e] = 0.f;
    for (int j = tid; j < E_ * D_; j += 256) {
        const float* xp = xs.p[j >> 10];
        int col = j & (D_ - 1);
        float4 w0 = *(const float4*)(gw + (long)j * 8);
        float4 w1 = *(const float4*)(gw + (long)j * 8 + 4);
#pragma unroll
        for (int t = 0; t < 4; t++) {
            float v = xp[(long)(b0 + t) * D_ + col];
            acc[t][0] = fmaf(v, w0.x, acc[t][0]); acc[t][1] = fmaf(v, w0.y, acc[t][1]);
            acc[t][2] = fmaf(v, w0.z, acc[t][2]); acc[t][3] = fmaf(v, w0.w, acc[t][3]);
            acc[t][4] = fmaf(v, w1.x, acc[t][4]); acc[t][5] = fmaf(v, w1.y, acc[t][5]);
            acc[t][6] = fmaf(v, w1.z, acc[t][6]); acc[t][7] = fmaf(v, w1.w, acc[t][7]);
        }
    }
#pragma unroll
    for (int o = 16; o > 0; o >>= 1)
#pragma unroll
        for (int t = 0; t < 4; t++)
#pragma unroll
            for (int e = 0; e < 8; e++)
                acc[t][e] += __shfl_down_sync(0xffffffffu, acc[t][e], o);
    __shared__ float s[8][4][8];
    int w = tid >> 5, lane = tid & 31;
    if (lane == 0)
#pragma unroll
        for (int t = 0; t < 4; t++)
#pragma unroll
            for (int e = 0; e < 8; e++) s[w][t][e] = acc[t][e];
    __syncthreads();
    if (tid < 4) {
        int t = tid, b = b0 + t;
        float lg[8];
#pragma unroll
        for (int e = 0; e < 8; e++) {
            float a = gb[e];
#pragma unroll
            for (int w2 = 0; w2 < 8; w2++) a += s[w2][t][e];
            lg[e] = a;
        }
        int i0 = 0;
        for (int e = 1; e < 8; e++) if (lg[e] > lg[i0]) i0 = e;
        int i1 = (i0 == 0) ? 1 : 0;
        for (int e = 0; e < 8; e++) if (e != i0 && lg[e] > lg[i1]) i1 = e;
        float ex = expf(lg[i1] - lg[i0]);
        float inv = 1.f / (1.f + ex);
        g_eidx[2 * b] = i0; g_eidx[2 * b + 1] = i1;
        g_wt[2 * b] = inv;  g_wt[2 * b + 1] = ex * inv;
        atomicAdd(&g_cnt[i0], 1);
        atomicAdd(&g_cnt[i1], 1);
    }
}

__global__ void k_scan() {
    if (threadIdx.x == 0) {
        int acc = 0;
        for (int e = 0; e < E_; e++) { g_off[e] = acc; g_cur[e] = acc; acc += g_cnt[e]; }
        g_off[E_] = acc;
    }
}

__global__ void k_fill() {
    int t = blockIdx.x * blockDim.x + threadIdx.x;
    if (t < S_) {
        int e = g_eidx[t];
        int pos = atomicAdd(&g_cur[e], 1);
        g_rows[pos] = t >> 1;
        g_sexp[pos] = e;
        g_slot[t] = pos;
    }
}

union UH4 { __half h[4]; uint2 u; };

__global__ void k_gather(XPtrs xs) {
    int sIdx = blockIdx.x;
    int e = g_sexp[sIdx];
    long t = g_rows[sIdx];
    const float4* src = (const float4*)(xs.p[e] + t * D_);
    __half* oh = g_xg + (long)sIdx * D_;
    for (int i = threadIdx.x; i < D_ / 4; i += 128) {
        float4 v = src[i];
        UH4 hv;
        hv.h[0] = __float2half_rn(v.x);
        hv.h[1] = __float2half_rn(v.y);
        hv.h[2] = __float2half_rn(v.z);
        hv.h[3] = __float2half_rn(v.w);
        *(uint2*)(oh + i * 4) = hv.u;
    }
}

// transpose: W[e][k][n] fp32 -> Wt[e][n][k] fp16
__global__ void k_convw(const float* __restrict__ W, __half* __restrict__ T, int K, int N) {
    __shared__ float t[32][33];
    int e = blockIdx.z;
    long base = (long)e * K * N;
    int n0 = blockIdx.x * 32, k0 = blockIdx.y * 32;
    int tx = threadIdx.x, ty = threadIdx.y;
#pragma unroll
    for (int i = 0; i < 32; i += 8)
        t[ty + i][tx] = W[base + (long)(k0 + ty + i) * N + n0 + tx];
    __syncthreads();
    long ob = (long)e * N * K;
#pragma unroll
    for (int i = 0; i < 32; i += 8)
        T[ob + (long)(n0 + ty + i) * K + k0 + tx] = __float2half_rn(t[tx][ty + i]);
}

// ---------------- HMMA GEMM (mma.sync fp16, single-term) ----------------
// BM=128, BN=256, BK=32, 256 threads (8 warps = 2m x 4n), warp tile 64x64.
// smem stage: A(10240 B) + B(20480 B) = 30720 B, pitch 40 halves (80 B).
// 4-stage cp.async pipeline, one __syncthreads per iteration.
#define A_B   10240
#define ST_B  30720
#define NST   4

template <int K, int N, bool RELU, bool HALF_OUT>
__global__ void __launch_bounds__(256, 1) k_mma(
    const __half* __restrict__ A, const __half* __restrict__ Bw,
    const float* __restrict__ bias,
    __half* __restrict__ oh, float* __restrict__ of) {
    const int e   = blockIdx.z;
    const int off = g_off[e];
    const int cnt = g_off[e + 1] - off;
    const int m0  = blockIdx.y * 128;
    if (m0 >= cnt) return;
    const int n0  = blockIdx.x * 256;
    const int arow0 = off + m0;

    extern __shared__ char smem[];
    __shared__ float sbias[256];
    const uint32_t sb = smem_u32(smem);

    const int tid = threadIdx.x, wid = tid >> 5, lane = tid & 31;
    sbias[tid] = bias[(long)e * N + n0 + tid];

    // ---- load plan: rA = tid>>2 (0..63), cq = tid&3 ----
    const int rA = tid >> 2, cq = tid & 3;
    long r0 = arow0 + rA;      if (r0 > S_ - 1) r0 = S_ - 1;
    long r1 = arow0 + rA + 64; if (r1 > S_ - 1) r1 = S_ - 1;
    const __half* a0 = A + r0 * (long)K + cq * 8;
    const __half* a1 = A + r1 * (long)K + cq * 8;
    const __half* bp = Bw + ((long)e * N + n0 + rA) * (long)K + cq * 8;
    const long bstep = 64L * K;
    const uint32_t sA = sb + rA * 80 + cq * 16;
    const uint32_t sB = sb + A_B + rA * 80 + cq * 16;

#define LOAD_STAGE(soff, koff) do {                                    \
    cp16(sA + (soff),           a0 + (koff));                          \
    cp16(sA + (soff) + 64 * 80, a1 + (koff));                          \
    _Pragma("unroll")                                                  \
    for (int j = 0; j < 4; j++)                                        \
        cp16(sB + (soff) + j * 64 * 80, bp + (koff) + j * bstep);      \
} while (0)

    LOAD_STAGE(0, 0);          CP_COMMIT();
    LOAD_STAGE(ST_B, 32);      CP_COMMIT();
    LOAD_STAGE(2 * ST_B, 64);  CP_COMMIT();

    // ---- warp tiling: 2m x 4n, warp tile 64x64 ----
    const int base_m = (wid & 1) * 64;
    const int base_n = (wid >> 1) * 64;
    const uint32_t arow = base_m + (lane & 15);
    const uint32_t acol = (lane >> 4) << 3;
    const uint32_t brow = base_n + ((lane >> 4) << 3) + (lane & 7);
    const uint32_t bcol = ((lane >> 3) & 1) << 3;

    float acc[4][8][4];
#pragma unroll
    for (int mi = 0; mi < 4; mi++)
#pragma unroll
        for (int nj = 0; nj < 8; nj++)
#pragma unroll
            for (int q = 0; q < 4; q++) acc[mi][nj][q] = 0.f;

    const int NIT = K / 32;
#pragma unroll 1
    for (int it = 0; it < NIT; it++) {
        CP_WAIT2();
        __syncthreads();
        const uint32_t st = sb + (it & (NST - 1)) * ST_B;
#pragma unroll
        for (int ks = 0; ks < 2; ks++) {
            uint32_t a[4][4], b[4][4];
            uint32_t ab = st + (arow * 40 + ks * 16 + acol) * 2;
            uint32_t bb = st + A_B + (brow * 40 + ks * 16 + bcol) * 2;
#pragma unroll
            for (int mi = 0; mi < 4; mi++) ldsm4(a[mi], ab + mi * 1280);
#pragma unroll
            for (int ni = 0; ni < 4; ni++) ldsm4(b[ni], bb + ni * 1280);
#pragma unroll
            for (int mi = 0; mi < 4; mi++)
#pragma unroll
                for (int ni = 0; ni < 4; ni++)
#pragma unroll
                    for (int h = 0; h < 2; h++)
                        mma16816(acc[mi][ni * 2 + h], a[mi], &b[ni][h * 2]);
        }
        if (it + 3 < NIT) {
            const uint32_t so = ((it + 3) & (NST - 1)) * ST_B;
            LOAD_STAGE(so, (it + 3) * 32);
        }
        CP_COMMIT();
    }
#undef LOAD_STAGE

    // ---- epilogue ----
#pragma unroll
    for (int mi = 0; mi < 4; mi++) {
        int gr0 = m0 + base_m + mi * 16 + (lane >> 2);
        bool v0 = gr0 < cnt, v1 = (gr0 + 8) < cnt;
        long s0 = (long)(off + gr0), s1 = s0 + 8;
#pragma unroll
        for (int nj = 0; nj < 8; nj++) {
            int col = base_n + nj * 8 + (lane & 3) * 2;
            float2 bv = *(float2*)&sbias[col];
            float x0 = acc[mi][nj][0] + bv.x;
            float x1 = acc[mi][nj][1] + bv.y;
            float x2 = acc[mi][nj][2] + bv.x;
            float x3 = acc[mi][nj][3] + bv.y;
            if (RELU) {
                x0 = fmaxf(x0, 0.f); x1 = fmaxf(x1, 0.f);
                x2 = fmaxf(x2, 0.f); x3 = fmaxf(x3, 0.f);
            }
            long gcol = n0 + col;
            if (HALF_OUT) {
                if (v0) {
                    __half2 hp; hp.x = __float2half_rn(x0); hp.y = __float2half_rn(x1);
                    *(__half2*)(oh + s0 * N + gcol) = hp;
                }
                if (v1) {
                    __half2 hp; hp.x = __float2half_rn(x2); hp.y = __float2half_rn(x3);
                    *(__half2*)(oh + s1 * N + gcol) = hp;
                }
            } else {
                if (v0) { float2 v; v.x = x0; v.y = x1; *(float2*)(of + s0 * N + gcol) = v; }
                if (v1) { float2 v; v.x = x2; v.y = x3; *(float2*)(of + s1 * N + gcol) = v; }
            }
        }
    }
}

// ---------------- combine ----------------
__global__ void k_combine(float* __restrict__ out) {
    int idx = blockIdx.x * 256 + threadIdx.x;
    int b = idx >> 8;
    int o4 = idx & 255;
    float w0 = g_wt[2 * b], w1 = g_wt[2 * b + 1];
    const float4* r0 = (const float4*)(g_eo + (long)g_slot[2 * b] * O_);
    const float4* r1 = (const float4*)(g_eo + (long)g_slot[2 * b + 1] * O_);
    float4 a = r0[o4], c = r1[o4], v;
    v.x = w0 * a.x + w1 * c.x;
    v.y = w0 * a.y + w1 * c.y;
    v.z = w0 * a.z + w1 * c.z;
    v.w = w0 * a.w + w1 * c.w;
    ((float4*)out)[idx] = v;
}

// ---------------- host ----------------
#define SMEM_DYN (NST * ST_B)

extern "C" void kernel_launch(void* const* d_in, const int* in_sizes, int n_in,
                              void* d_out, int out_size) {
    XPtrs xs;
    for (int i = 0; i < E_; i++) xs.p[i] = (const float*)d_in[i];
    const float* gw    = (const float*)d_in[8];
    const float* gb    = (const float*)d_in[9];
    const float* w_in  = (const float*)d_in[10];
    const float* b_in  = (const float*)d_in[11];
    const float* w_h   = (const float*)d_in[12];
    const float* b_h   = (const float*)d_in[13];
    const float* w_out = (const float*)d_in[14];
    const float* b_out = (const float*)d_in[15];
    float* out = (float*)d_out;

    void *xg, *h1, *h2, *win, *wh, *wo, *eo;
    cudaGetSymbolAddress(&xg, g_xg);
    cudaGetSymbolAddress(&h1, g_h1);
    cudaGetSymbolAddress(&h2, g_h2);
    cudaGetSymbolAddress(&win, g_win);
    cudaGetSymbolAddress(&wh, g_wh);
    cudaGetSymbolAddress(&wo, g_wo);
    cudaGetSymbolAddress(&eo, g_eo);

    cudaFuncSetAttribute((const void*)k_mma<1024, 2048, true, true>,
                         cudaFuncAttributeMaxDynamicSharedMemorySize, SMEM_DYN);
    cudaFuncSetAttribute((const void*)k_mma<2048, 2048, true, true>,
                         cudaFuncAttributeMaxDynamicSharedMemorySize, SMEM_DYN);
    cudaFuncSetAttribute((const void*)k_mma<2048, 1024, false, false>,
                         cudaFuncAttributeMaxDynamicSharedMemorySize, SMEM_DYN);

    k_zero<<<1, 32>>>();
    k_gate<<<B_ / 4, 256>>>(xs, gw, gb);
    k_scan<<<1, 32>>>();
    k_fill<<<S_ / 256, 256>>>();
    k_gather<<<S_, 128>>>(xs);
    k_convw<<<dim3(H_ / 32, D_ / 32, E_), dim3(32, 8)>>>(w_in, (__half*)win, D_, H_);
    k_convw<<<dim3(H_ / 32, H_ / 32, E_), dim3(32, 8)>>>(w_h, (__half*)wh, H_, H_);
    k_convw<<<dim3(O_ / 32, H_ / 32, E_), dim3(32, 8)>>>(w_out, (__half*)wo, H_, O_);

    k_mma<1024, 2048, true, true><<<dim3(H_ / 256, S_ / 128, E_), 256, SMEM_DYN>>>(
        (const __half*)xg, (const __half*)win, b_in, (__half*)h1, nullptr);
    k_mma<2048, 2048, true, true><<<dim3(H_ / 256, S_ / 128, E_), 256, SMEM_DYN>>>(
        (const __half*)h1, (const __half*)wh, b_h, (__half*)h2, nullptr);
    k_mma<2048, 1024, false, false><<<dim3(O_ / 256, S_ / 128, E_), 256, SMEM_DYN>>>(
        (const __half*)h2, (const __half*)wo, b_out, nullptr, (float*)eo);

    k_combine<<<(B_ * O_ / 4) / 256, 256>>>(out);
}